// round 8
// baseline (speedup 1.0000x reference)
#include <cuda_runtime.h>
#include <cstdint>

// ---------------- problem constants ----------------
#define Bc 4
#define Lc 8192
#define Dc 512
#define Hc 8
#define DKc 64
#define Ec 65           // DK + PD
#define Fc 520          // H * E
#define FP 544          // padded F (multiple of 32)
#define EH 68           // padded per-head width for KH/VH (16B aligned)
#define NSPLIT 16
#define LCHUNK (Lc / NSPLIT)

#define ATT_ELEMS  ((size_t)Bc * Lc * Dc)
#define ATTN_ELEMS ((size_t)Bc * Hc * Ec * Ec)

// ---------------- scratch (device globals; no allocs allowed) ----------------
__device__ float g_QC[(size_t)Bc * Lc * FP];        // concat q, tf32-rounded
__device__ float g_KH[(size_t)Bc * Hc * Lc * EH];   // LN'd k, fp32 exact
__device__ float g_VH[(size_t)Bc * Hc * Lc * EH];   // LN'd v, fp32 exact
__device__ float g_part[(size_t)Bc * Hc * NSPLIT * Ec * Ec];
__device__ float g_W2T[(size_t)Bc * Dc * FP];       // folded fc weights, tf32-rounded
__device__ float g_Wc[3][(size_t)Dc * Dc];          // tf32-rounded Wq/Wk/Wv

// ============================================================================
// helpers
// ============================================================================
__device__ __forceinline__ uint32_t smem_u32(const void* p) {
    uint32_t a;
    asm("{ .reg .u64 t; cvta.to.shared.u64 t, %1; cvt.u32.u64 %0, t; }" : "=r"(a) : "l"(p));
    return a;
}
__device__ __forceinline__ uint32_t f2tf32(float x) {
    uint32_t r;
    asm("cvt.rna.tf32.f32 %0, %1;" : "=r"(r) : "f"(x));
    return r;
}
__device__ __forceinline__ float f2tf32f(float x) {
    return __uint_as_float(f2tf32(x));
}
__device__ __forceinline__ void cp16(uint32_t dst, const float* src) {
    asm volatile("cp.async.ca.shared.global [%0], [%1], 16;" :: "r"(dst), "l"(src));
}
#define CP_COMMIT() asm volatile("cp.async.commit_group;" ::: "memory")
#define CP_WAIT0()  asm volatile("cp.async.wait_group 0;" ::: "memory")
#define CP_WAIT1()  asm volatile("cp.async.wait_group 1;" ::: "memory")

__device__ __forceinline__ void mma_tf32(float c[4], const uint32_t a[4], const uint32_t b[2]) {
    asm volatile(
        "mma.sync.aligned.m16n8k8.row.col.f32.tf32.tf32.f32 "
        "{%0,%1,%2,%3}, {%4,%5,%6,%7}, {%8,%9}, {%0,%1,%2,%3};"
        : "+f"(c[0]), "+f"(c[1]), "+f"(c[2]), "+f"(c[3])
        : "r"(a[0]), "r"(a[1]), "r"(a[2]), "r"(a[3]), "r"(b[0]), "r"(b[1]));
}

// ============================================================================
// GEMM mainloop: 128x128 CTA tile, 128 threads (4 warps), warp tile 64x64.
// K-block 32, cp.async 2-stage, 73.7KB smem -> 2 CTAs/SM.
// acc[4][8][4] (m16 x n8 fragments).
// ============================================================================
#define SSTR 36                        // smem row stride (floats), conflict-free
#define ATILE (128 * SSTR)             // 4608 floats per operand per stage
#define STAGEF (2 * ATILE)             // 9216 floats per stage
#define NSTAGE 2
#define SMEM_GEMM (NSTAGE * STAGEF * 4)   // 73728 bytes
#define NTHR 128

__device__ __forceinline__ void gemm_copy_stage(
    const float* __restrict__ A, const float* __restrict__ Bw,
    int lda, int m0, int n0, int kb, uint32_t sbase, int crow)
{
    const int s = kb & 1;
    const int k0 = kb << 5;
    uint32_t as = sbase + (uint32_t)(s * STAGEF) * 4u;
    uint32_t bs = as + (uint32_t)ATILE * 4u;
    const float* ap = A + (size_t)(m0 + crow) * lda + k0;
    const float* bp = Bw + (size_t)(n0 + crow) * lda + k0;
    uint32_t doff = (uint32_t)(crow * SSTR) * 4u;
#pragma unroll
    for (int i = 0; i < 8; i++) {
        cp16(as + doff + 16u * i, ap + 4 * i);
        cp16(bs + doff + 16u * i, bp + 4 * i);
    }
}

template<bool CA, bool CB>
__device__ __forceinline__ void gemm_mainloop(
    const float* __restrict__ A, const float* __restrict__ Bw,
    int lda, int NKB, int m0, int n0,
    float* smf, uint32_t sbase, float acc[4][8][4])
{
    const int tid = threadIdx.x;
    const int wid = tid >> 5;
    const int lane = tid & 31;
    const int g = lane >> 2;
    const int t = lane & 3;
    const int mw = (wid >> 1) * 64;
    const int nw = (wid & 1) * 64;
    const int crow = tid;                 // copy row 0..127

    gemm_copy_stage(A, Bw, lda, m0, n0, 0, sbase, crow);
    CP_COMMIT();
    if (NKB > 1) {
        gemm_copy_stage(A, Bw, lda, m0, n0, 1, sbase, crow);
        CP_COMMIT();
    }

#pragma unroll 1
    for (int kb = 0; kb < NKB; kb++) {
        if (kb + 1 < NKB) { CP_WAIT1(); } else { CP_WAIT0(); }
        __syncthreads();

        const float* As = smf + (kb & 1) * STAGEF;
        const float* Bs = As + ATILE;
#pragma unroll
        for (int kk = 0; kk < 32; kk += 8) {
            uint32_t af[4][4];
#pragma unroll
            for (int i = 0; i < 4; i++) {
                const float* base = As + (mw + 16 * i) * SSTR + kk;
                float v0 = base[(g)     * SSTR + t];
                float v1 = base[(g + 8) * SSTR + t];
                float v2 = base[(g)     * SSTR + t + 4];
                float v3 = base[(g + 8) * SSTR + t + 4];
                af[i][0] = CA ? f2tf32(v0) : __float_as_uint(v0);
                af[i][1] = CA ? f2tf32(v1) : __float_as_uint(v1);
                af[i][2] = CA ? f2tf32(v2) : __float_as_uint(v2);
                af[i][3] = CA ? f2tf32(v3) : __float_as_uint(v3);
            }
            uint32_t bf[8][2];
#pragma unroll
            for (int j = 0; j < 8; j++) {
                const float* base = Bs + (nw + 8 * j + g) * SSTR + kk;
                float w0 = base[t];
                float w1 = base[t + 4];
                bf[j][0] = CB ? f2tf32(w0) : __float_as_uint(w0);
                bf[j][1] = CB ? f2tf32(w1) : __float_as_uint(w1);
            }
#pragma unroll
            for (int i = 0; i < 4; i++)
#pragma unroll
                for (int j = 0; j < 8; j++)
                    mma_tf32(acc[i][j], af[i], bf[j]);
        }
        __syncthreads();

        if (kb + 2 < NKB) {
            gemm_copy_stage(A, Bw, lda, m0, n0, kb + 2, sbase, crow);
            CP_COMMIT();
        }
    }
}

// ============================================================================
// Kernel W: pre-round Wq/Wk/Wv to tf32
// ============================================================================
__global__ void wcvt(const float* __restrict__ Wq, const float* __restrict__ Wk,
                     const float* __restrict__ Wv)
{
    const int op = blockIdx.y;
    const float* W = (op == 0) ? Wq : (op == 1) ? Wk : Wv;
    const int i = blockIdx.x * 256 + threadIdx.x;
    g_Wc[op][i] = f2tf32f(W[i]);
}

// ============================================================================
// Kernel A: fused projection + LN + concat.  grid (4, 256, 3), 128 thr.
// ============================================================================
#define CSTR 132

__global__ void __launch_bounds__(NTHR, 2)
proj_fused(const float* __restrict__ Xq, const float* __restrict__ Xk,
           const float* __restrict__ Xv,
           const float* __restrict__ bq, const float* __restrict__ bk,
           const float* __restrict__ bv,
           const float* __restrict__ gK, const float* __restrict__ betaK,
           const float* __restrict__ gV, const float* __restrict__ betaV,
           const float* __restrict__ pos)
{
    extern __shared__ __align__(16) float smf[];
    const uint32_t sbase = smem_u32(smf);
    const int mode = blockIdx.z;
    const float* A    = (mode == 0) ? Xq : (mode == 1) ? Xk : Xv;
    const float* W    = g_Wc[mode];
    const float* bias = (mode == 0) ? bq : (mode == 1) ? bk : bv;
    const float* gamm = (mode == 1) ? gK : gV;
    const float* beta = (mode == 1) ? betaK : betaV;

    const int m0 = blockIdx.y * 128;
    const int n0 = blockIdx.x * 128;

    float acc[4][8][4] = {};
    gemm_mainloop<true, false>(A, W, Dc, Dc / 32, m0, n0, smf, sbase, acc);

    // ---- stage tile (+bias) into smem ----
    __syncthreads();
    const int tid = threadIdx.x;
    const int wid = tid >> 5;
    const int lane = tid & 31;
    const int g = lane >> 2;
    const int t = lane & 3;
    const int mw = (wid >> 1) * 64;
    const int nw = (wid & 1) * 64;

#pragma unroll
    for (int i = 0; i < 4; i++) {
        const int r0 = mw + 16 * i + g;
#pragma unroll
        for (int j = 0; j < 8; j++) {
            const int col = nw + 8 * j + 2 * t;
            float2 bv2 = *(const float2*)(bias + n0 + col);
            smf[r0 * CSTR + col]       = acc[i][j][0] + bv2.x;
            smf[r0 * CSTR + col + 1]   = acc[i][j][1] + bv2.y;
            smf[(r0 + 8) * CSTR + col]     = acc[i][j][2] + bv2.x;
            smf[(r0 + 8) * CSTR + col + 1] = acc[i][j][3] + bv2.y;
        }
    }
    __syncthreads();

    // ---- per-row epilogue: 4 warps x 32 rows ----
    for (int rr = 0; rr < 32; rr++) {
        const int r = wid * 32 + rr;
        const int m = m0 + r;                 // = b*L + l
        const int b = m >> 13, l = m & (Lc - 1);
        const float pv = pos[m];
#pragma unroll
        for (int hh = 0; hh < 2; hh++) {
            const int h = (n0 >> 6) + hh;
            float x0 = smf[r * CSTR + 64 * hh + lane];
            float x1 = smf[r * CSTR + 64 * hh + lane + 32];
            if (mode == 0) {
                // q concat, tf32-rounded (out_gemm reads it cvt-free)
                float* qrow = &g_QC[(size_t)m * FP + h * Ec];
                if (lane == 0) qrow[0] = f2tf32f(pv);
                qrow[1 + lane] = f2tf32f(x0);
                qrow[1 + lane + 32] = f2tf32f(x1);
                if (hh == 1 && n0 == 384 && lane < (FP - Fc))
                    g_QC[(size_t)m * FP + Fc + lane] = 0.0f;
            } else {
                float s = x0 + x1, sq = x0 * x0 + x1 * x1;
#pragma unroll
                for (int off = 16; off; off >>= 1) {
                    s  += __shfl_xor_sync(0xffffffffu, s,  off);
                    sq += __shfl_xor_sync(0xffffffffu, sq, off);
                }
                float mean = s * (1.0f / 64.0f);
                float var = sq * (1.0f / 64.0f) - mean * mean;
                float rstd = rsqrtf(var + 1e-5f);
                float y0 = (x0 - mean) * rstd * gamm[h * DKc + lane] + beta[h * DKc + lane];
                float y1 = (x1 - mean) * rstd * gamm[h * DKc + lane + 32] + beta[h * DKc + lane + 32];
                float* orow = ((mode == 1) ? g_KH : g_VH) +
                              (((size_t)b * Hc + h) * Lc + l) * EH;
                if (lane == 0) orow[0] = pv;
                orow[1 + lane] = y0;
                orow[1 + lane + 32] = y1;
                if (lane < 2) orow[66 + lane] = 0.0f;   // pad cols
            }
        }
    }
}

// ============================================================================
// Kernel B: attn partials  part[b,h,s] = K_chunk^T @ V_chunk  (fp32 exact)
// ============================================================================
__global__ void __launch_bounds__(256)
attn_partial()
{
    __shared__ __align__(16) float ks[2][16][80];
    __shared__ __align__(16) float vs[2][16][80];
    const int split = blockIdx.x, h = blockIdx.y, b = blockIdx.z;
    const int tid = threadIdx.x;
    const int td = tid >> 4;
    const int te = tid & 15;

    for (int i = tid; i < 2 * 16 * 80; i += 256) {
        ((float*)ks)[i] = 0.0f;
        ((float*)vs)[i] = 0.0f;
    }
    __syncthreads();

    const float* Kbase = g_KH + (((size_t)b * Hc + h) * Lc + (size_t)split * LCHUNK) * EH;
    const float* Vbase = g_VH + (((size_t)b * Hc + h) * Lc + (size_t)split * LCHUNK) * EH;

    auto issue = [&](int it) {
        const int buf = it & 1;
        const int l0 = it * 16;
#pragma unroll
        for (int c = 0; c < 3; c++) {
            int idx = tid + c * 256;
            if (idx < 544) {
                int arr = idx >= 272;
                int i2 = arr ? idx - 272 : idx;
                int row = i2 / 17, c4 = i2 % 17;
                const float* src = (arr ? Vbase : Kbase) + (size_t)(l0 + row) * EH + 4 * c4;
                uint32_t dst = smem_u32(arr ? &vs[buf][row][4 * c4] : &ks[buf][row][4 * c4]);
                cp16(dst, src);
            }
        }
        CP_COMMIT();
    };

    issue(0);

    float acc[5][5] = {};
#pragma unroll 1
    for (int it = 0; it < LCHUNK / 16; it++) {
        CP_WAIT0();
        __syncthreads();
        if (it + 1 < LCHUNK / 16) issue(it + 1);
        const int buf = it & 1;
#pragma unroll
        for (int r = 0; r < 16; r++) {
            float kv[5], vv[5];
#pragma unroll
            for (int i = 0; i < 5; i++) kv[i] = ks[buf][r][td + 16 * i];
#pragma unroll
            for (int j = 0; j < 5; j++) vv[j] = vs[buf][r][te + 16 * j];
#pragma unroll
            for (int i = 0; i < 5; i++)
#pragma unroll
                for (int j = 0; j < 5; j++)
                    acc[i][j] += kv[i] * vv[j];
        }
        __syncthreads();
    }

    float* out = &g_part[(((size_t)b * Hc + h) * NSPLIT + split) * Ec * Ec];
#pragma unroll
    for (int i = 0; i < 5; i++) {
        int d = td + 16 * i;
        if (d >= Ec) continue;
#pragma unroll
        for (int j = 0; j < 5; j++) {
            int e = te + 16 * j;
            if (e < Ec) out[d * Ec + e] = acc[i][j];
        }
    }
}

// ============================================================================
// Kernel C: reduce partials, scale by 1/L
// ============================================================================
__global__ void attn_reduce(float* __restrict__ attn_out)
{
    const size_t idx = (size_t)blockIdx.x * blockDim.x + threadIdx.x;
    if (idx >= ATTN_ELEMS) return;
    const size_t bh = idx / (Ec * Ec);
    const size_t de = idx % (Ec * Ec);
    float s = 0.0f;
#pragma unroll
    for (int sp = 0; sp < NSPLIT; sp++)
        s += g_part[(bh * NSPLIT + sp) * (Ec * Ec) + de];
    attn_out[idx] = s * (1.0f / (float)Lc);
}

// ============================================================================
// Kernel D: W2T[b,o,h*65+d] = sum_e attn[b,h,d,e]*fcW[o,h*65+e]   (tf32-rounded)
// ============================================================================
__global__ void __launch_bounds__(256)
w2t_kernel(const float* __restrict__ attn, const float* __restrict__ fcW)
{
    const int og = blockIdx.x;          // 0..7 (64 o's each)
    const int bh = blockIdx.y;          // 0..31
    const int b = bh >> 3, h = bh & 7;
    __shared__ float sa[Ec * 68];       // sa[e*68 + d] = attn[d][e]  (transposed)
    __shared__ float sw[64 * 66];       // sw[o*66 + e] = fcW row
    const int tid = threadIdx.x;

    for (int i = tid; i < Ec * Ec; i += 256) {
        int d = i / Ec, e = i % Ec;
        sa[e * 68 + d] = attn[((size_t)bh * Ec + d) * Ec + e];
    }
    for (int i = tid; i < 64 * Ec; i += 256) {
        int o = i / Ec, e = i % Ec;
        sw[o * 66 + e] = fcW[(size_t)(og * 64 + o) * Fc + h * Ec + e];
    }
    __syncthreads();

    for (int idx = tid; idx < 64 * Ec; idx += 256) {
        int o = idx / Ec, d = idx % Ec;   // consecutive threads -> consecutive d
        const float* wr = &sw[o * 66];
        float s = 0.0f;
#pragma unroll
        for (int e = 0; e < Ec; e++) s += wr[e] * sa[e * 68 + d];
        g_W2T[((size_t)b * Dc + og * 64 + o) * FP + h * Ec + d] = f2tf32f(s);
    }
    if (h == 0) {
        for (int i = tid; i < 64 * (FP - Fc); i += 256) {
            int o = og * 64 + i / (FP - Fc), cc = Fc + i % (FP - Fc);
            g_W2T[((size_t)b * Dc + o) * FP + cc] = 0.0f;
        }
    }
}

// ============================================================================
// Kernel E: out[b] = QC[b] @ W2T[b]^T + fcb.  grid (4, 64, 4), 128 thr.
// ============================================================================
__global__ void __launch_bounds__(NTHR, 2)
out_gemm(const float* __restrict__ fcb, float* __restrict__ out)
{
    extern __shared__ __align__(16) float smf[];
    const uint32_t sbase = smem_u32(smf);
    const int b = blockIdx.z;
    const float* A  = g_QC + (size_t)b * Lc * FP;
    const float* Bw = g_W2T + (size_t)b * Dc * FP;
    float* C = out + (size_t)b * Lc * Dc;

    const int m0 = blockIdx.y * 128;
    const int n0 = blockIdx.x * 128;

    float acc[4][8][4] = {};
    gemm_mainloop<false, false>(A, Bw, FP, FP / 32, m0, n0, smf, sbase, acc);

    const int tid = threadIdx.x;
    const int wid = tid >> 5;
    const int lane = tid & 31;
    const int g = lane >> 2;
    const int t = lane & 3;
    const int mw = (wid >> 1) * 64;
    const int nw = (wid & 1) * 64;

#pragma unroll
    for (int i = 0; i < 4; i++) {
        const int row0 = m0 + mw + 16 * i + g;
#pragma unroll
        for (int j = 0; j < 8; j++) {
            const int col = n0 + nw + 8 * j + 2 * t;
            float2 bv = *(const float2*)(fcb + col);
            float2 o0, o1;
            o0.x = acc[i][j][0] + bv.x;  o0.y = acc[i][j][1] + bv.y;
            o1.x = acc[i][j][2] + bv.x;  o1.y = acc[i][j][3] + bv.y;
            *(float2*)(C + (size_t)row0 * Dc + col) = o0;
            *(float2*)(C + (size_t)(row0 + 8) * Dc + col) = o1;
        }
    }
}

// ============================================================================
// launch
// ============================================================================
extern "C" void kernel_launch(void* const* d_in, const int* in_sizes, int n_in,
                              void* d_out, int out_size)
{
    const float* query = (const float*)d_in[0];
    const float* key   = (const float*)d_in[1];
    const float* value = (const float*)d_in[2];
    const float* pos   = (const float*)d_in[3];
    const float* Wq    = (const float*)d_in[4];
    const float* bq    = (const float*)d_in[5];
    const float* Wk    = (const float*)d_in[6];
    const float* bk    = (const float*)d_in[7];
    const float* Wv    = (const float*)d_in[8];
    const float* bv    = (const float*)d_in[9];
    const float* gK    = (const float*)d_in[10];
    const float* betaK = (const float*)d_in[11];
    const float* gV    = (const float*)d_in[12];
    const float* betaV = (const float*)d_in[13];
    const float* fcW   = (const float*)d_in[14];
    const float* fcb   = (const float*)d_in[15];

    float* att_out  = (float*)d_out;
    float* attn_out = att_out + ATT_ELEMS;

    cudaFuncSetAttribute(proj_fused, cudaFuncAttributeMaxDynamicSharedMemorySize, SMEM_GEMM);
    cudaFuncSetAttribute(out_gemm,  cudaFuncAttributeMaxDynamicSharedMemorySize, SMEM_GEMM);

    // 0) pre-round weights to tf32
    wcvt<<<dim3(Dc * Dc / 256, 3), 256>>>(Wq, Wk, Wv);
    // 1) fused projections + LN + concat
    proj_fused<<<dim3(4, 256, 3), NTHR, SMEM_GEMM>>>(query, key, value,
                                                      bq, bk, bv,
                                                      gK, betaK, gV, betaV, pos);
    // 2) attn partials (deterministic split over L, fp32 exact)
    attn_partial<<<dim3(NSPLIT, Hc, Bc), 256>>>();
    // 3) reduce + scale -> attn output
    attn_reduce<<<(unsigned)((ATTN_ELEMS + 255) / 256), 256>>>(attn_out);
    // 4) fold attn into fc weights (tf32-rounded at store)
    w2t_kernel<<<dim3(8, Bc * Hc), 256>>>(attn_out, fcW);
    // 5) output GEMM (cvt-free), batched over z
    out_gemm<<<dim3(4, 64, Bc), NTHR, SMEM_GEMM>>>(fcb, att_out);
}

// round 9
// speedup vs baseline: 1.9812x; 1.9812x over previous
#include <cuda_runtime.h>
#include <cuda_fp16.h>
#include <cstdint>

// ---------------- problem constants ----------------
#define Bc 4
#define Lc 8192
#define Dc 512
#define Hc 8
#define DKc 64
#define Ec 65           // DK + PD
#define Fc 520          // H * E
#define FP 544          // padded F (multiple of 32)
#define EH 68           // padded per-head width for KH/VH (16B aligned)
#define NSPLIT 16
#define LCHUNK (Lc / NSPLIT)

#define ATT_ELEMS  ((size_t)Bc * Lc * Dc)
#define ATTN_ELEMS ((size_t)Bc * Hc * Ec * Ec)
#define BLD ((size_t)Bc * Lc * Dc)

// ---------------- scratch (device globals; no allocs allowed) ----------------
__device__ __half g_Xh[3][BLD];                     // fp16 query/key/value
__device__ __half g_Wh[3][(size_t)Dc * Dc];         // fp16 Wq/Wk/Wv
__device__ __half g_QCh[(size_t)Bc * Lc * FP];      // concat q, fp16, pad zeroed
__device__ float  g_KH[(size_t)Bc * Hc * Lc * EH];  // LN'd k, fp32 exact
__device__ float  g_VH[(size_t)Bc * Hc * Lc * EH];  // LN'd v, fp32 exact
__device__ float  g_part[(size_t)Bc * Hc * NSPLIT * Ec * Ec];
__device__ __half g_W2Th[(size_t)Bc * Dc * FP];     // folded fc weights, fp16

// ============================================================================
// helpers
// ============================================================================
__device__ __forceinline__ uint32_t smem_u32(const void* p) {
    uint32_t a;
    asm("{ .reg .u64 t; cvta.to.shared.u64 t, %1; cvt.u32.u64 %0, t; }" : "=r"(a) : "l"(p));
    return a;
}
__device__ __forceinline__ void cp16(uint32_t dst, const void* src) {
    asm volatile("cp.async.ca.shared.global [%0], [%1], 16;" :: "r"(dst), "l"(src));
}
#define CP_COMMIT() asm volatile("cp.async.commit_group;" ::: "memory")
#define CP_WAIT0()  asm volatile("cp.async.wait_group 0;" ::: "memory")
#define CP_WAIT1()  asm volatile("cp.async.wait_group 1;" ::: "memory")

__device__ __forceinline__ void mma_f16(float c[4], const uint32_t a[4], const uint32_t b[2]) {
    asm volatile(
        "mma.sync.aligned.m16n8k16.row.col.f32.f16.f16.f32 "
        "{%0,%1,%2,%3}, {%4,%5,%6,%7}, {%8,%9}, {%0,%1,%2,%3};"
        : "+f"(c[0]), "+f"(c[1]), "+f"(c[2]), "+f"(c[3])
        : "r"(a[0]), "r"(a[1]), "r"(a[2]), "r"(a[3]), "r"(b[0]), "r"(b[1]));
}

// ============================================================================
// fp16 GEMM mainloop: C[M,N] = A[M,K] @ B[N,K]^T, fp32 accum.
// 128x128 CTA tile, 256 thr (8 warps, warp tile 64x32), K-block 32,
// cp.async 3-stage, single sync per K-block. Stage = 20.5KB -> 61.4KB smem.
// ============================================================================
#define SSTRH 40                        // smem row stride in halfs (80B, conflict-free)
#define ATILEH (128 * SSTRH)            // 5120 halfs per operand per stage
#define STAGEH (2 * ATILEH)             // 10240 halfs per stage
#define NSTAGE 3
#define SMEM_MAIN (NSTAGE * STAGEH * 2) // 61440 bytes
#define SMEM_PROJ (128 * 132 * 4)       // 67584 bytes (epilogue staging)

__device__ __forceinline__ void gemm_copy_stage(
    const __half* __restrict__ A, const __half* __restrict__ Bw,
    int lda, int m0, int n0, int kb, uint32_t sbase, int r0, int c)
{
    const int s = kb % NSTAGE;
    const int k0 = kb << 5;
    uint32_t as = sbase + (uint32_t)(s * STAGEH) * 2u;
    uint32_t bs = as + (uint32_t)ATILEH * 2u;
#pragma unroll
    for (int rr = 0; rr < 2; rr++) {
        const int row = r0 + rr * 64;
        uint32_t doff = (uint32_t)(row * SSTRH + c * 8) * 2u;
        cp16(as + doff, A + (size_t)(m0 + row) * lda + k0 + c * 8);
        cp16(bs + doff, Bw + (size_t)(n0 + row) * lda + k0 + c * 8);
    }
}

__device__ __forceinline__ void gemm_mainloop(
    const __half* __restrict__ A, const __half* __restrict__ Bw,
    int lda, int NKB, int m0, int n0,
    const __half* smh, uint32_t sbase, float acc[4][4][4])
{
    const int tid = threadIdx.x;
    const int wid = tid >> 5;
    const int lane = tid & 31;
    const int g = lane >> 2;
    const int t = lane & 3;
    const int mw = (wid >> 2) * 64;
    const int nw = (wid & 3) * 32;
    const int r0 = tid >> 2;              // copy row 0..63 (+64)
    const int cc = tid & 3;               // copy chunk

    gemm_copy_stage(A, Bw, lda, m0, n0, 0, sbase, r0, cc);
    CP_COMMIT();
    gemm_copy_stage(A, Bw, lda, m0, n0, 1, sbase, r0, cc);
    CP_COMMIT();

#pragma unroll 1
    for (int kb = 0; kb < NKB; kb++) {
        if (kb + 1 < NKB) { CP_WAIT1(); } else { CP_WAIT0(); }
        __syncthreads();
        // buffer (kb+2)%3 was computed at kb-1; sync above proves it's free.
        if (kb + 2 < NKB) {
            gemm_copy_stage(A, Bw, lda, m0, n0, kb + 2, sbase, r0, cc);
            CP_COMMIT();
        }

        const __half* As = smh + (kb % NSTAGE) * STAGEH;
        const __half* Bs = As + ATILEH;
#pragma unroll
        for (int kk = 0; kk < 32; kk += 16) {
            uint32_t af[4][4];
#pragma unroll
            for (int i = 0; i < 4; i++) {
                const __half* base = As + (mw + 16 * i + g) * SSTRH + kk + 2 * t;
                af[i][0] = *(const uint32_t*)(base);
                af[i][1] = *(const uint32_t*)(base + 8 * SSTRH);
                af[i][2] = *(const uint32_t*)(base + 8);
                af[i][3] = *(const uint32_t*)(base + 8 * SSTRH + 8);
            }
            uint32_t bf[4][2];
#pragma unroll
            for (int j = 0; j < 4; j++) {
                const __half* base = Bs + (nw + 8 * j + g) * SSTRH + kk + 2 * t;
                bf[j][0] = *(const uint32_t*)(base);
                bf[j][1] = *(const uint32_t*)(base + 8);
            }
#pragma unroll
            for (int i = 0; i < 4; i++)
#pragma unroll
                for (int j = 0; j < 4; j++)
                    mma_f16(acc[i][j], af[i], bf[j]);
        }
    }
}

// ============================================================================
// Kernel X: convert inputs to fp16 (vectorized, float4 -> 2x half2)
// ============================================================================
__global__ void xcvt(const float* __restrict__ Xq, const float* __restrict__ Xk,
                     const float* __restrict__ Xv)
{
    const int op = blockIdx.y;
    const float* X = (op == 0) ? Xq : (op == 1) ? Xk : Xv;
    const size_t i4 = (size_t)blockIdx.x * 256 + threadIdx.x;
    float4 v = ((const float4*)X)[i4];
    __half2* dst = (__half2*)(g_Xh[op] + i4 * 4);
    dst[0] = __floats2half2_rn(v.x, v.y);
    dst[1] = __floats2half2_rn(v.z, v.w);
}

__global__ void wcvt(const float* __restrict__ Wq, const float* __restrict__ Wk,
                     const float* __restrict__ Wv)
{
    const int op = blockIdx.y;
    const float* W = (op == 0) ? Wq : (op == 1) ? Wk : Wv;
    const size_t i4 = (size_t)blockIdx.x * 256 + threadIdx.x;
    float4 v = ((const float4*)W)[i4];
    __half2* dst = (__half2*)(g_Wh[op] + i4 * 4);
    dst[0] = __floats2half2_rn(v.x, v.y);
    dst[1] = __floats2half2_rn(v.z, v.w);
}

// ============================================================================
// Kernel A: fused projection + LN + concat.  grid (4, 256, 3), 256 thr.
// ============================================================================
#define CSTR 132

__global__ void __launch_bounds__(256, 2)
proj_fused(const float* __restrict__ bq, const float* __restrict__ bk,
           const float* __restrict__ bv,
           const float* __restrict__ gK, const float* __restrict__ betaK,
           const float* __restrict__ gV, const float* __restrict__ betaV,
           const float* __restrict__ pos)
{
    extern __shared__ __align__(16) char smraw[];
    __half* smh = (__half*)smraw;
    float* smf = (float*)smraw;
    const uint32_t sbase = smem_u32(smraw);
    const int mode = blockIdx.z;
    const __half* A = g_Xh[mode];
    const __half* W = g_Wh[mode];
    const float* bias = (mode == 0) ? bq : (mode == 1) ? bk : bv;
    const float* gamm = (mode == 1) ? gK : gV;
    const float* beta = (mode == 1) ? betaK : betaV;

    const int m0 = blockIdx.y * 128;
    const int n0 = blockIdx.x * 128;

    float acc[4][4][4] = {};
    gemm_mainloop(A, W, Dc, Dc / 32, m0, n0, smh, sbase, acc);

    // ---- stage tile (+bias) into smem as fp32 ----
    __syncthreads();
    const int tid = threadIdx.x;
    const int wid = tid >> 5;
    const int lane = tid & 31;
    const int g = lane >> 2;
    const int t = lane & 3;
    const int mw = (wid >> 2) * 64;
    const int nw = (wid & 3) * 32;

#pragma unroll
    for (int i = 0; i < 4; i++) {
        const int r0 = mw + 16 * i + g;
#pragma unroll
        for (int j = 0; j < 4; j++) {
            const int col = nw + 8 * j + 2 * t;
            float2 bv2 = *(const float2*)(bias + n0 + col);
            smf[r0 * CSTR + col]       = acc[i][j][0] + bv2.x;
            smf[r0 * CSTR + col + 1]   = acc[i][j][1] + bv2.y;
            smf[(r0 + 8) * CSTR + col]     = acc[i][j][2] + bv2.x;
            smf[(r0 + 8) * CSTR + col + 1] = acc[i][j][3] + bv2.y;
        }
    }
    __syncthreads();

    // ---- per-row epilogue: 8 warps x 16 rows ----
    for (int rr = 0; rr < 16; rr++) {
        const int r = wid * 16 + rr;
        const int m = m0 + r;                 // = b*L + l
        const int b = m >> 13, l = m & (Lc - 1);
        const float pv = pos[m];
#pragma unroll
        for (int hh = 0; hh < 2; hh++) {
            const int h = (n0 >> 6) + hh;
            float x0 = smf[r * CSTR + 64 * hh + lane];
            float x1 = smf[r * CSTR + 64 * hh + lane + 32];
            if (mode == 0) {
                // q concat, fp16 (out_gemm reads it directly)
                __half* qrow = &g_QCh[(size_t)m * FP + h * Ec];
                if (lane == 0) qrow[0] = __float2half_rn(pv);
                qrow[1 + lane] = __float2half_rn(x0);
                qrow[1 + lane + 32] = __float2half_rn(x1);
                if (hh == 1 && n0 == 384 && lane < (FP - Fc))
                    g_QCh[(size_t)m * FP + Fc + lane] = __float2half_rn(0.0f);
            } else {
                float s = x0 + x1, sq = x0 * x0 + x1 * x1;
#pragma unroll
                for (int off = 16; off; off >>= 1) {
                    s  += __shfl_xor_sync(0xffffffffu, s,  off);
                    sq += __shfl_xor_sync(0xffffffffu, sq, off);
                }
                float mean = s * (1.0f / 64.0f);
                float var = sq * (1.0f / 64.0f) - mean * mean;
                float rstd = rsqrtf(var + 1e-5f);
                float y0 = (x0 - mean) * rstd * gamm[h * DKc + lane] + beta[h * DKc + lane];
                float y1 = (x1 - mean) * rstd * gamm[h * DKc + lane + 32] + beta[h * DKc + lane + 32];
                float* orow = ((mode == 1) ? g_KH : g_VH) +
                              (((size_t)b * Hc + h) * Lc + l) * EH;
                if (lane == 0) orow[0] = pv;
                orow[1 + lane] = y0;
                orow[1 + lane + 32] = y1;
                if (lane < 2) orow[66 + lane] = 0.0f;   // pad cols
            }
        }
    }
}

// ============================================================================
// Kernel B: attn partials  part[b,h,s] = K_chunk^T @ V_chunk  (fp32 exact)
// ============================================================================
__global__ void __launch_bounds__(256)
attn_partial()
{
    __shared__ __align__(16) float ks[2][16][80];
    __shared__ __align__(16) float vs[2][16][80];
    const int split = blockIdx.x, h = blockIdx.y, b = blockIdx.z;
    const int tid = threadIdx.x;
    const int td = tid >> 4;
    const int te = tid & 15;

    for (int i = tid; i < 2 * 16 * 80; i += 256) {
        ((float*)ks)[i] = 0.0f;
        ((float*)vs)[i] = 0.0f;
    }
    __syncthreads();

    const float* Kbase = g_KH + (((size_t)b * Hc + h) * Lc + (size_t)split * LCHUNK) * EH;
    const float* Vbase = g_VH + (((size_t)b * Hc + h) * Lc + (size_t)split * LCHUNK) * EH;

    auto issue = [&](int it) {
        const int buf = it & 1;
        const int l0 = it * 16;
#pragma unroll
        for (int c = 0; c < 3; c++) {
            int idx = tid + c * 256;
            if (idx < 544) {
                int arr = idx >= 272;
                int i2 = arr ? idx - 272 : idx;
                int row = i2 / 17, c4 = i2 % 17;
                const float* src = (arr ? Vbase : Kbase) + (size_t)(l0 + row) * EH + 4 * c4;
                uint32_t dst = smem_u32(arr ? &vs[buf][row][4 * c4] : &ks[buf][row][4 * c4]);
                cp16(dst, src);
            }
        }
        CP_COMMIT();
    };

    issue(0);

    float acc[5][5] = {};
#pragma unroll 1
    for (int it = 0; it < LCHUNK / 16; it++) {
        CP_WAIT0();
        __syncthreads();
        if (it + 1 < LCHUNK / 16) issue(it + 1);
        const int buf = it & 1;
#pragma unroll
        for (int r = 0; r < 16; r++) {
            float kv[5], vv[5];
#pragma unroll
            for (int i = 0; i < 5; i++) kv[i] = ks[buf][r][td + 16 * i];
#pragma unroll
            for (int j = 0; j < 5; j++) vv[j] = vs[buf][r][te + 16 * j];
#pragma unroll
            for (int i = 0; i < 5; i++)
#pragma unroll
                for (int j = 0; j < 5; j++)
                    acc[i][j] += kv[i] * vv[j];
        }
        __syncthreads();
    }

    float* out = &g_part[(((size_t)b * Hc + h) * NSPLIT + split) * Ec * Ec];
#pragma unroll
    for (int i = 0; i < 5; i++) {
        int d = td + 16 * i;
        if (d >= Ec) continue;
#pragma unroll
        for (int j = 0; j < 5; j++) {
            int e = te + 16 * j;
            if (e < Ec) out[d * Ec + e] = acc[i][j];
        }
    }
}

// ============================================================================
// Kernel C: reduce partials, scale by 1/L
// ============================================================================
__global__ void attn_reduce(float* __restrict__ attn_out)
{
    const size_t idx = (size_t)blockIdx.x * blockDim.x + threadIdx.x;
    if (idx >= ATTN_ELEMS) return;
    const size_t bh = idx / (Ec * Ec);
    const size_t de = idx % (Ec * Ec);
    float s = 0.0f;
#pragma unroll
    for (int sp = 0; sp < NSPLIT; sp++)
        s += g_part[(bh * NSPLIT + sp) * (Ec * Ec) + de];
    attn_out[idx] = s * (1.0f / (float)Lc);
}

// ============================================================================
// Kernel D: W2Th[b,o,h*65+d] = sum_e attn[b,h,d,e]*fcW[o,h*65+e]   (fp16 out)
// ============================================================================
__global__ void __launch_bounds__(256)
w2t_kernel(const float* __restrict__ attn, const float* __restrict__ fcW)
{
    const int og = blockIdx.x;          // 0..7 (64 o's each)
    const int bh = blockIdx.y;          // 0..31
    const int b = bh >> 3, h = bh & 7;
    __shared__ float sa[Ec * 68];       // sa[e*68 + d] = attn[d][e]  (transposed)
    __shared__ float sw[64 * 66];       // sw[o*66 + e] = fcW row
    const int tid = threadIdx.x;

    for (int i = tid; i < Ec * Ec; i += 256) {
        int d = i / Ec, e = i % Ec;
        sa[e * 68 + d] = attn[((size_t)bh * Ec + d) * Ec + e];
    }
    for (int i = tid; i < 64 * Ec; i += 256) {
        int o = i / Ec, e = i % Ec;
        sw[o * 66 + e] = fcW[(size_t)(og * 64 + o) * Fc + h * Ec + e];
    }
    __syncthreads();

    for (int idx = tid; idx < 64 * Ec; idx += 256) {
        int o = idx / Ec, d = idx % Ec;
        const float* wr = &sw[o * 66];
        float s = 0.0f;
#pragma unroll
        for (int e = 0; e < Ec; e++) s += wr[e] * sa[e * 68 + d];
        g_W2Th[((size_t)b * Dc + og * 64 + o) * FP + h * Ec + d] = __float2half_rn(s);
    }
    if (h == 0) {
        for (int i = tid; i < 64 * (FP - Fc); i += 256) {
            int o = og * 64 + i / (FP - Fc), cc = Fc + i % (FP - Fc);
            g_W2Th[((size_t)b * Dc + o) * FP + cc] = __float2half_rn(0.0f);
        }
    }
}

// ============================================================================
// Kernel E: out[b] = QCh[b] @ W2Th[b]^T + fcb.  grid (4, 64, 4), 256 thr.
// ============================================================================
__global__ void __launch_bounds__(256, 2)
out_gemm(const float* __restrict__ fcb, float* __restrict__ out)
{
    extern __shared__ __align__(16) char smraw[];
    __half* smh = (__half*)smraw;
    const uint32_t sbase = smem_u32(smraw);
    const int b = blockIdx.z;
    const __half* A  = g_QCh + (size_t)b * Lc * FP;
    const __half* Bw = g_W2Th + (size_t)b * Dc * FP;
    float* C = out + (size_t)b * Lc * Dc;

    const int m0 = blockIdx.y * 128;
    const int n0 = blockIdx.x * 128;

    float acc[4][4][4] = {};
    gemm_mainloop(A, Bw, FP, FP / 32, m0, n0, smh, sbase, acc);

    const int tid = threadIdx.x;
    const int wid = tid >> 5;
    const int lane = tid & 31;
    const int g = lane >> 2;
    const int t = lane & 3;
    const int mw = (wid >> 2) * 64;
    const int nw = (wid & 3) * 32;

#pragma unroll
    for (int i = 0; i < 4; i++) {
        const int row0 = m0 + mw + 16 * i + g;
#pragma unroll
        for (int j = 0; j < 4; j++) {
            const int col = n0 + nw + 8 * j + 2 * t;
            float2 bv = *(const float2*)(fcb + col);
            float2 o0, o1;
            o0.x = acc[i][j][0] + bv.x;  o0.y = acc[i][j][1] + bv.y;
            o1.x = acc[i][j][2] + bv.x;  o1.y = acc[i][j][3] + bv.y;
            *(float2*)(C + (size_t)row0 * Dc + col) = o0;
            *(float2*)(C + (size_t)(row0 + 8) * Dc + col) = o1;
        }
    }
}

// ============================================================================
// launch
// ============================================================================
extern "C" void kernel_launch(void* const* d_in, const int* in_sizes, int n_in,
                              void* d_out, int out_size)
{
    const float* query = (const float*)d_in[0];
    const float* key   = (const float*)d_in[1];
    const float* value = (const float*)d_in[2];
    const float* pos   = (const float*)d_in[3];
    const float* Wq    = (const float*)d_in[4];
    const float* bq    = (const float*)d_in[5];
    const float* Wk    = (const float*)d_in[6];
    const float* bk    = (const float*)d_in[7];
    const float* Wv    = (const float*)d_in[8];
    const float* bv    = (const float*)d_in[9];
    const float* gK    = (const float*)d_in[10];
    const float* betaK = (const float*)d_in[11];
    const float* gV    = (const float*)d_in[12];
    const float* betaV = (const float*)d_in[13];
    const float* fcW   = (const float*)d_in[14];
    const float* fcb   = (const float*)d_in[15];

    float* att_out  = (float*)d_out;
    float* attn_out = att_out + ATT_ELEMS;

    cudaFuncSetAttribute(proj_fused, cudaFuncAttributeMaxDynamicSharedMemorySize, SMEM_PROJ);
    cudaFuncSetAttribute(out_gemm,  cudaFuncAttributeMaxDynamicSharedMemorySize, SMEM_MAIN);

    // 0) convert inputs + weights to fp16
    xcvt<<<dim3((unsigned)(BLD / 4 / 256), 3), 256>>>(query, key, value);
    wcvt<<<dim3(Dc * Dc / 4 / 256, 3), 256>>>(Wq, Wk, Wv);
    // 1) fused projections + LN + concat (fp16 MMA, fp32 accum)
    proj_fused<<<dim3(4, 256, 3), 256, SMEM_PROJ>>>(bq, bk, bv,
                                                     gK, betaK, gV, betaV, pos);
    // 2) attn partials (deterministic split over L, fp32 exact)
    attn_partial<<<dim3(NSPLIT, Hc, Bc), 256>>>();
    // 3) reduce + scale -> attn output
    attn_reduce<<<(unsigned)((ATTN_ELEMS + 255) / 256), 256>>>(attn_out);
    // 4) fold attn into fc weights (fp16 out)
    w2t_kernel<<<dim3(8, Bc * Hc), 256>>>(attn_out, fcW);
    // 5) output GEMM (fp16 MMA), batched over z
    out_gemm<<<dim3(4, 64, Bc), 256, SMEM_MAIN>>>(fcb, att_out);
}